// round 1
// baseline (speedup 1.0000x reference)
#include <cuda_runtime.h>
#include <cuda_bf16.h>
#include <math.h>

// Problem constants
#define SEQ    128
#define BATCH  32
#define NTOKEN 32000
#define NINP   1024
#define NHID   1024
#define MROWS  (SEQ * BATCH)          // 4096

// ---------------- scratch (no runtime allocation allowed) ----------------
__device__ float g_xin[MROWS * NHID];   // 16 MB
__device__ float g_hs [MROWS * NHID];   // 16 MB
__device__ unsigned g_arrive;
__device__ unsigned g_release;

// ---------------- reset barrier counters (each launch/replay) ----------------
__global__ void reset_barrier_kernel() {
    g_arrive = 0u;
    g_release = 0u;
}

// ---------------- generic fp32 GEMM: C[M,N] = A[M,K] * B[N,K]^T + bias[N] ----
// BM=128, BN=128, BK=16, 256 threads, 8x8 per-thread tile.
// GATHER: A row m comes from A + rows[m]*K (embedding lookup).
template <bool GATHER>
__global__ __launch_bounds__(256)
void gemm_tn_kernel(const float* __restrict__ A,
                    const int*   __restrict__ rows,
                    const float* __restrict__ B,
                    const float* __restrict__ bias,
                    float*       __restrict__ C,
                    int M, int N, int K)
{
    __shared__ float As[16][128];
    __shared__ float Bs[16][128];

    const int t  = threadIdx.x;
    const int m0 = blockIdx.y * 128;
    const int n0 = blockIdx.x * 128;

    const int tn = t & 15;       // 0..15 -> col group
    const int tm = t >> 4;       // 0..15 -> row group

    // load assignment: 2 threads per tile-row, each loads 2 float4 along K
    const int lr = t >> 1;            // 0..127 row within tile
    const int kq = (t & 1) * 8;       // 0 or 8

    long a_row = GATHER ? (long)rows[m0 + lr] : (long)(m0 + lr);
    const float* Ap = A + a_row * (long)K;
    const float* Bp = B + (long)(n0 + lr) * (long)K;

    float acc[8][8];
#pragma unroll
    for (int i = 0; i < 8; ++i)
#pragma unroll
        for (int j = 0; j < 8; ++j) acc[i][j] = 0.0f;

    for (int k0 = 0; k0 < K; k0 += 16) {
        // ---- load A tile (transposed into smem) ----
        float4 a0 = *(const float4*)(Ap + k0 + kq);
        float4 a1 = *(const float4*)(Ap + k0 + kq + 4);
        float4 b0 = *(const float4*)(Bp + k0 + kq);
        float4 b1 = *(const float4*)(Bp + k0 + kq + 4);
        __syncthreads();
        As[kq + 0][lr] = a0.x; As[kq + 1][lr] = a0.y;
        As[kq + 2][lr] = a0.z; As[kq + 3][lr] = a0.w;
        As[kq + 4][lr] = a1.x; As[kq + 5][lr] = a1.y;
        As[kq + 6][lr] = a1.z; As[kq + 7][lr] = a1.w;
        Bs[kq + 0][lr] = b0.x; Bs[kq + 1][lr] = b0.y;
        Bs[kq + 2][lr] = b0.z; Bs[kq + 3][lr] = b0.w;
        Bs[kq + 4][lr] = b1.x; Bs[kq + 5][lr] = b1.y;
        Bs[kq + 6][lr] = b1.z; Bs[kq + 7][lr] = b1.w;
        __syncthreads();

        // ---- compute ----
#pragma unroll
        for (int k = 0; k < 16; ++k) {
            float4 af0 = *(const float4*)&As[k][tm * 8];
            float4 af1 = *(const float4*)&As[k][tm * 8 + 4];
            float4 bf0 = *(const float4*)&Bs[k][tn * 8];
            float4 bf1 = *(const float4*)&Bs[k][tn * 8 + 4];
            float av[8] = {af0.x, af0.y, af0.z, af0.w, af1.x, af1.y, af1.z, af1.w};
            float bv[8] = {bf0.x, bf0.y, bf0.z, bf0.w, bf1.x, bf1.y, bf1.z, bf1.w};
#pragma unroll
            for (int i = 0; i < 8; ++i)
#pragma unroll
                for (int j = 0; j < 8; ++j)
                    acc[i][j] = fmaf(av[i], bv[j], acc[i][j]);
        }
    }

    // ---- epilogue: add bias, store ----
    float bb[8];
#pragma unroll
    for (int j = 0; j < 8; ++j) bb[j] = bias[n0 + tn * 8 + j];

#pragma unroll
    for (int i = 0; i < 8; ++i) {
        long crow = (long)(m0 + tm * 8 + i) * (long)N + n0 + tn * 8;
        float4 v0, v1;
        v0.x = acc[i][0] + bb[0]; v0.y = acc[i][1] + bb[1];
        v0.z = acc[i][2] + bb[2]; v0.w = acc[i][3] + bb[3];
        v1.x = acc[i][4] + bb[4]; v1.y = acc[i][5] + bb[5];
        v1.z = acc[i][6] + bb[6]; v1.w = acc[i][7] + bb[7];
        *(float4*)(C + crow)     = v0;
        *(float4*)(C + crow + 4) = v1;
    }
}

// ---------------- persistent RNN scan ----------------
// 128 blocks, 256 threads. Block jb owns hidden cols [jb*8, jb*8+8).
// W_hh slice (8 x 1024) resident in smem. Split-K across 8 warps.
#define HS_STRIDE 1028   // padded: bank-conflict-free float4 row access

__device__ __forceinline__ void grid_barrier(unsigned gen) {
    __syncthreads();
    if (threadIdx.x == 0) {
        __threadfence();
        if (atomicAdd(&g_arrive, 1u) == gridDim.x - 1) {
            g_arrive = 0u;
            __threadfence();
            atomicExch(&g_release, gen);
        } else {
            while (*(volatile unsigned*)&g_release < gen) { }
        }
        __threadfence();
    }
    __syncthreads();
}

__global__ __launch_bounds__(256)
void scan_kernel(const float* __restrict__ xin,
                 const float* __restrict__ h0,
                 const float* __restrict__ W_hh,
                 const float* __restrict__ b_hh,
                 const float* __restrict__ alpha,
                 float*       __restrict__ hs)
{
    extern __shared__ float sm[];
    float* Wsh = sm;                          // 8 * 1024
    float* hsh = sm + 8 * 1024;               // 32 * HS_STRIDE
    float* red = hsh + 32 * HS_STRIDE;        // 8 * 32 * 8 = 2048

    const int t  = threadIdx.x;
    const int jb = blockIdx.x;
    const int j0 = jb * 8;

    // preload W_hh rows j0..j0+7 (32 KB)
    {
        const float4* src = (const float4*)(W_hh + (long)j0 * NHID);
        float4* dst = (float4*)Wsh;
        for (int i = t; i < 8 * NHID / 4; i += 256) dst[i] = src[i];
    }

    const int kg = t >> 5;   // warp id 0..7 : K-split group
    const int b  = t & 31;   // batch lane

    const int b2  = t >> 3;  // 0..31 for reduce/writeback
    const int jj2 = t & 7;
    const float bh = b_hh[j0 + jj2];

    for (int s = 0; s < SEQ; ++s) {
        const float* hprev = (s == 0) ? h0 : (hs + (long)(s - 1) * BATCH * NHID);

        __syncthreads();
        // stage h_prev into padded smem
        for (int i = t; i < BATCH * NHID / 4; i += 256) {
            float4 v = ((const float4*)hprev)[i];
            int bb = i >> 8;        // row (1024/4 = 256 float4 per row)
            int k4 = i & 255;
            *(float4*)&hsh[bb * HS_STRIDE + k4 * 4] = v;
        }
        __syncthreads();

        float acc[8];
#pragma unroll
        for (int jj = 0; jj < 8; ++jj) acc[jj] = 0.0f;

        const float* hrow = &hsh[b * HS_STRIDE + kg * 128];
        const float* wbase = &Wsh[kg * 128];
#pragma unroll 4
        for (int k = 0; k < 128; k += 4) {
            float4 hv = *(const float4*)&hrow[k];
#pragma unroll
            for (int jj = 0; jj < 8; ++jj) {
                float4 wv = *(const float4*)&wbase[jj * NHID + k];
                acc[jj] += hv.x * wv.x + hv.y * wv.y + hv.z * wv.z + hv.w * wv.w;
            }
        }

#pragma unroll
        for (int jj = 0; jj < 8; ++jj) red[(kg * 32 + b) * 8 + jj] = acc[jj];
        __syncthreads();

        // final reduce + activation + write: thread -> (b2, jj2)
        {
            float sum = 0.0f;
#pragma unroll
            for (int kk = 0; kk < 8; ++kk) sum += red[(kk * 32 + b2) * 8 + jj2];
            float val = xin[(long)(s * BATCH + b2) * NHID + j0 + jj2] + sum + bh;
            float hnew = alpha[s] * tanhf(val);
            hs[(long)(s * BATCH + b2) * NHID + j0 + jj2] = hnew;
        }

        grid_barrier((unsigned)(s + 1));
    }
}

// ---------------- final hidden copy ----------------
__global__ void copy_hidden_kernel(const float* __restrict__ hs, float* __restrict__ dst) {
    int i = blockIdx.x * blockDim.x + threadIdx.x;
    if (i < BATCH * NHID) dst[i] = hs[(long)(SEQ - 1) * BATCH * NHID + i];
}

// ---------------- launch ----------------
extern "C" void kernel_launch(void* const* d_in, const int* in_sizes, int n_in,
                              void* d_out, int out_size)
{
    const int*   input  = (const int*)  d_in[0];
    const float* hidden = (const float*)d_in[1];
    const float* emb_W  = (const float*)d_in[2];
    const float* W_ih   = (const float*)d_in[3];
    const float* W_hh   = (const float*)d_in[4];
    const float* b_ih   = (const float*)d_in[5];
    const float* b_hh   = (const float*)d_in[6];
    const float* alpha  = (const float*)d_in[7];
    const float* dec_W  = (const float*)d_in[8];
    const float* dec_b  = (const float*)d_in[9];

    float* decoded  = (float*)d_out;                                   // [S,B,NTOKEN]
    float* hidden_f = (float*)d_out + (long)MROWS * NTOKEN;            // [B,NHID]

    void *xin_p, *hs_p;
    cudaGetSymbolAddress(&xin_p, g_xin);
    cudaGetSymbolAddress(&hs_p,  g_hs);
    float* xin = (float*)xin_p;
    float* hs  = (float*)hs_p;

    const int scan_smem = (8 * 1024 + 32 * HS_STRIDE + 2048) * (int)sizeof(float);
    cudaFuncSetAttribute(scan_kernel, cudaFuncAttributeMaxDynamicSharedMemorySize, scan_smem);

    // 1) xin = emb_W[input] @ W_ih^T + b_ih   [4096 x 1024]
    gemm_tn_kernel<true><<<dim3(NHID / 128, MROWS / 128), 256>>>(
        emb_W, input, W_ih, b_ih, xin, MROWS, NHID, NINP);

    // 2) recurrence
    reset_barrier_kernel<<<1, 1>>>();
    scan_kernel<<<128, 256, scan_smem>>>(xin, hidden, W_hh, b_hh, alpha, hs);

    // 3) final hidden
    copy_hidden_kernel<<<(BATCH * NHID + 255) / 256, 256>>>(hs, hidden_f);

    // 4) decoder: decoded = hs @ dec_W^T + dec_b   [4096 x 32000]
    gemm_tn_kernel<false><<<dim3(NTOKEN / 128, MROWS / 128), 256>>>(
        hs, nullptr, dec_W, dec_b, decoded, MROWS, NTOKEN, NHID);
}

// round 2
// speedup vs baseline: 2.4458x; 2.4458x over previous
#include <cuda_runtime.h>
#include <cuda_bf16.h>
#include <math.h>
#include <stdint.h>

// Problem constants
#define SEQ    128
#define BATCH  32
#define NTOKEN 32000
#define NINP   1024
#define NHID   1024
#define MROWS  (SEQ * BATCH)          // 4096

// ---------------- scratch (no runtime allocation allowed) ----------------
__device__ float g_xin[MROWS * NHID];        // 16 MB
__device__ float g_hs [MROWS * NHID];        // 16 MB
__device__ float g_hs_t32[MROWS * NHID];     // 16 MB (tf32 bits)
__device__ float g_decW_t32[NTOKEN * NHID];  // 131 MB (tf32 bits)
__device__ unsigned g_arrive;
__device__ unsigned g_release;

// ---------------- reset barrier counters (each launch/replay) ----------------
__global__ void reset_barrier_kernel() {
    g_arrive = 0u;
    g_release = 0u;
}

// ---------------- fp32 -> tf32 bit conversion (elementwise) ----------------
__global__ __launch_bounds__(256)
void cvt_tf32_kernel(const float* __restrict__ in, float* __restrict__ out, long n)
{
    long i = ((long)blockIdx.x * blockDim.x + threadIdx.x) * 4;
    long stride = (long)gridDim.x * blockDim.x * 4;
    for (; i < n; i += stride) {
        float4 v = *(const float4*)(in + i);
        uint4 o;
        asm("cvt.rna.tf32.f32 %0, %1;" : "=r"(o.x) : "f"(v.x));
        asm("cvt.rna.tf32.f32 %0, %1;" : "=r"(o.y) : "f"(v.y));
        asm("cvt.rna.tf32.f32 %0, %1;" : "=r"(o.z) : "f"(v.z));
        asm("cvt.rna.tf32.f32 %0, %1;" : "=r"(o.w) : "f"(v.w));
        *(uint4*)(out + i) = o;
    }
}

// ---------------- generic fp32 GEMM (used for xin): C = A[M,K]*B[N,K]^T + bias
template <bool GATHER>
__global__ __launch_bounds__(256)
void gemm_tn_kernel(const float* __restrict__ A,
                    const int*   __restrict__ rows,
                    const float* __restrict__ B,
                    const float* __restrict__ bias,
                    float*       __restrict__ C,
                    int M, int N, int K)
{
    __shared__ float As[16][128];
    __shared__ float Bs[16][128];

    const int t  = threadIdx.x;
    const int m0 = blockIdx.y * 128;
    const int n0 = blockIdx.x * 128;

    const int tn = t & 15;
    const int tm = t >> 4;

    const int lr = t >> 1;
    const int kq = (t & 1) * 8;

    long a_row = GATHER ? (long)rows[m0 + lr] : (long)(m0 + lr);
    const float* Ap = A + a_row * (long)K;
    const float* Bp = B + (long)(n0 + lr) * (long)K;

    float acc[8][8];
#pragma unroll
    for (int i = 0; i < 8; ++i)
#pragma unroll
        for (int j = 0; j < 8; ++j) acc[i][j] = 0.0f;

    for (int k0 = 0; k0 < K; k0 += 16) {
        float4 a0 = *(const float4*)(Ap + k0 + kq);
        float4 a1 = *(const float4*)(Ap + k0 + kq + 4);
        float4 b0 = *(const float4*)(Bp + k0 + kq);
        float4 b1 = *(const float4*)(Bp + k0 + kq + 4);
        __syncthreads();
        As[kq + 0][lr] = a0.x; As[kq + 1][lr] = a0.y;
        As[kq + 2][lr] = a0.z; As[kq + 3][lr] = a0.w;
        As[kq + 4][lr] = a1.x; As[kq + 5][lr] = a1.y;
        As[kq + 6][lr] = a1.z; As[kq + 7][lr] = a1.w;
        Bs[kq + 0][lr] = b0.x; Bs[kq + 1][lr] = b0.y;
        Bs[kq + 2][lr] = b0.z; Bs[kq + 3][lr] = b0.w;
        Bs[kq + 4][lr] = b1.x; Bs[kq + 5][lr] = b1.y;
        Bs[kq + 6][lr] = b1.z; Bs[kq + 7][lr] = b1.w;
        __syncthreads();

#pragma unroll
        for (int k = 0; k < 16; ++k) {
            float4 af0 = *(const float4*)&As[k][tm * 8];
            float4 af1 = *(const float4*)&As[k][tm * 8 + 4];
            float4 bf0 = *(const float4*)&Bs[k][tn * 8];
            float4 bf1 = *(const float4*)&Bs[k][tn * 8 + 4];
            float av[8] = {af0.x, af0.y, af0.z, af0.w, af1.x, af1.y, af1.z, af1.w};
            float bv[8] = {bf0.x, bf0.y, bf0.z, bf0.w, bf1.x, bf1.y, bf1.z, bf1.w};
#pragma unroll
            for (int i = 0; i < 8; ++i)
#pragma unroll
                for (int j = 0; j < 8; ++j)
                    acc[i][j] = fmaf(av[i], bv[j], acc[i][j]);
        }
    }

    float bb[8];
#pragma unroll
    for (int j = 0; j < 8; ++j) bb[j] = bias[n0 + tn * 8 + j];

#pragma unroll
    for (int i = 0; i < 8; ++i) {
        long crow = (long)(m0 + tm * 8 + i) * (long)N + n0 + tn * 8;
        float4 v0, v1;
        v0.x = acc[i][0] + bb[0]; v0.y = acc[i][1] + bb[1];
        v0.z = acc[i][2] + bb[2]; v0.w = acc[i][3] + bb[3];
        v1.x = acc[i][4] + bb[4]; v1.y = acc[i][5] + bb[5];
        v1.z = acc[i][6] + bb[6]; v1.w = acc[i][7] + bb[7];
        *(float4*)(C + crow)     = v0;
        *(float4*)(C + crow + 4) = v1;
    }
}

// ---------------- tf32 tensor-core GEMM: C[M,N] = A[M,K]*B[N,K]^T + bias ----
// A, B hold tf32-converted bits (stored as float). 128x128x32 tile, 8 warps,
// warp tile 64x32 (m16n8k8 grid of 4x4). cp.async double-buffered.
#define TBM 128
#define TBN 128
#define TBK 32
#define TSTR 36   // smem row stride in floats (conflict-free frags)

__device__ __forceinline__ uint32_t smem_u32(const void* p) {
    return (uint32_t)__cvta_generic_to_shared(p);
}

__global__ __launch_bounds__(256, 2)
void gemm_tf32_kernel(const float* __restrict__ A,
                      const float* __restrict__ B,
                      const float* __restrict__ bias,
                      float*       __restrict__ C,
                      int M, int N, int K)
{
    extern __shared__ float smem[];
    float* As = smem;                       // [2][TBM*TSTR]
    float* Bs = smem + 2 * TBM * TSTR;      // [2][TBN*TSTR]

    const int t    = threadIdx.x;
    const int m0   = blockIdx.x * TBM;
    const int n0   = blockIdx.y * TBN;
    const int lane = t & 31;
    const int warp = t >> 5;
    const int wm   = warp & 1;      // 2 m-subtiles of 64
    const int wn   = warp >> 1;     // 4 n-subtiles of 32
    const int g    = lane >> 2;     // group 0..7
    const int tg   = lane & 3;      // 0..3

    float acc[4][4][4];
#pragma unroll
    for (int mi = 0; mi < 4; ++mi)
#pragma unroll
        for (int ni = 0; ni < 4; ++ni)
#pragma unroll
            for (int r = 0; r < 4; ++r) acc[mi][ni][r] = 0.0f;

    const int nkt = K / TBK;

    // async tile load: 1024 16B-chunks per operand, 4 per thread each
    auto issue = [&](int buf, int kt) {
        const int k0 = kt * TBK;
#pragma unroll
        for (int i = 0; i < 4; ++i) {
            int c   = t + i * 256;
            int row = c >> 3;
            int kc  = c & 7;
            uint32_t sa = smem_u32(&As[buf * TBM * TSTR + row * TSTR + kc * 4]);
            const float* ga = A + (long)(m0 + row) * K + k0 + kc * 4;
            asm volatile("cp.async.cg.shared.global [%0], [%1], 16;" :: "r"(sa), "l"(ga));
            uint32_t sb = smem_u32(&Bs[buf * TBN * TSTR + row * TSTR + kc * 4]);
            const float* gb = B + (long)(n0 + row) * K + k0 + kc * 4;
            asm volatile("cp.async.cg.shared.global [%0], [%1], 16;" :: "r"(sb), "l"(gb));
        }
        asm volatile("cp.async.commit_group;");
    };

    issue(0, 0);

    for (int kt = 0; kt < nkt; ++kt) {
        int buf = kt & 1;
        if (kt + 1 < nkt) issue(buf ^ 1, kt + 1);
        asm volatile("cp.async.wait_group 1;");
        __syncthreads();

        const float* Ab = As + buf * TBM * TSTR;
        const float* Bb = Bs + buf * TBN * TSTR;

#pragma unroll
        for (int kk = 0; kk < 4; ++kk) {
            const int kb = kk * 8;
            uint32_t a[4][4];
            uint32_t b[4][2];
#pragma unroll
            for (int mi = 0; mi < 4; ++mi) {
                int r0 = wm * 64 + mi * 16 + g;
                a[mi][0] = __float_as_uint(Ab[r0 * TSTR + kb + tg]);
                a[mi][1] = __float_as_uint(Ab[(r0 + 8) * TSTR + kb + tg]);
                a[mi][2] = __float_as_uint(Ab[r0 * TSTR + kb + tg + 4]);
                a[mi][3] = __float_as_uint(Ab[(r0 + 8) * TSTR + kb + tg + 4]);
            }
#pragma unroll
            for (int ni = 0; ni < 4; ++ni) {
                int nn = wn * 32 + ni * 8 + g;
                b[ni][0] = __float_as_uint(Bb[nn * TSTR + kb + tg]);
                b[ni][1] = __float_as_uint(Bb[nn * TSTR + kb + tg + 4]);
            }
#pragma unroll
            for (int mi = 0; mi < 4; ++mi)
#pragma unroll
                for (int ni = 0; ni < 4; ++ni) {
                    asm volatile(
                        "mma.sync.aligned.m16n8k8.row.col.f32.tf32.tf32.f32 "
                        "{%0,%1,%2,%3}, {%4,%5,%6,%7}, {%8,%9}, {%0,%1,%2,%3};\n"
                        : "+f"(acc[mi][ni][0]), "+f"(acc[mi][ni][1]),
                          "+f"(acc[mi][ni][2]), "+f"(acc[mi][ni][3])
                        : "r"(a[mi][0]), "r"(a[mi][1]), "r"(a[mi][2]), "r"(a[mi][3]),
                          "r"(b[ni][0]), "r"(b[ni][1]));
                }
        }
        __syncthreads();
    }

    // epilogue
#pragma unroll
    for (int mi = 0; mi < 4; ++mi) {
        int rbase = m0 + wm * 64 + mi * 16 + g;
#pragma unroll
        for (int ni = 0; ni < 4; ++ni) {
            int cc = n0 + wn * 32 + ni * 8 + 2 * tg;
            float b0 = bias[cc], b1 = bias[cc + 1];
            float2 v0 = make_float2(acc[mi][ni][0] + b0, acc[mi][ni][1] + b1);
            float2 v1 = make_float2(acc[mi][ni][2] + b0, acc[mi][ni][3] + b1);
            *(float2*)(C + (long)rbase * N + cc)       = v0;
            *(float2*)(C + (long)(rbase + 8) * N + cc) = v1;
        }
    }
}

// ---------------- persistent RNN scan ----------------
#define HS_STRIDE 1028

__device__ __forceinline__ void grid_barrier(unsigned gen) {
    __syncthreads();
    if (threadIdx.x == 0) {
        __threadfence();
        if (atomicAdd(&g_arrive, 1u) == gridDim.x - 1) {
            g_arrive = 0u;
            __threadfence();
            atomicExch(&g_release, gen);
        } else {
            while (*(volatile unsigned*)&g_release < gen) { }
        }
        __threadfence();
    }
    __syncthreads();
}

__global__ __launch_bounds__(256)
void scan_kernel(const float* __restrict__ xin,
                 const float* __restrict__ h0,
                 const float* __restrict__ W_hh,
                 const float* __restrict__ b_hh,
                 const float* __restrict__ alpha,
                 float*       __restrict__ hs)
{
    extern __shared__ float sm[];
    float* Wsh = sm;
    float* hsh = sm + 8 * 1024;
    float* red = hsh + 32 * HS_STRIDE;

    const int t  = threadIdx.x;
    const int jb = blockIdx.x;
    const int j0 = jb * 8;

    {
        const float4* src = (const float4*)(W_hh + (long)j0 * NHID);
        float4* dst = (float4*)Wsh;
        for (int i = t; i < 8 * NHID / 4; i += 256) dst[i] = src[i];
    }

    const int kg = t >> 5;
    const int b  = t & 31;
    const int b2  = t >> 3;
    const int jj2 = t & 7;
    const float bh = b_hh[j0 + jj2];

    for (int s = 0; s < SEQ; ++s) {
        const float* hprev = (s == 0) ? h0 : (hs + (long)(s - 1) * BATCH * NHID);

        __syncthreads();
        for (int i = t; i < BATCH * NHID / 4; i += 256) {
            float4 v = ((const float4*)hprev)[i];
            int bb = i >> 8;
            int k4 = i & 255;
            *(float4*)&hsh[bb * HS_STRIDE + k4 * 4] = v;
        }
        __syncthreads();

        float acc[8];
#pragma unroll
        for (int jj = 0; jj < 8; ++jj) acc[jj] = 0.0f;

        const float* hrow = &hsh[b * HS_STRIDE + kg * 128];
        const float* wbase = &Wsh[kg * 128];
#pragma unroll 4
        for (int k = 0; k < 128; k += 4) {
            float4 hv = *(const float4*)&hrow[k];
#pragma unroll
            for (int jj = 0; jj < 8; ++jj) {
                float4 wv = *(const float4*)&wbase[jj * NHID + k];
                acc[jj] += hv.x * wv.x + hv.y * wv.y + hv.z * wv.z + hv.w * wv.w;
            }
        }

#pragma unroll
        for (int jj = 0; jj < 8; ++jj) red[(kg * 32 + b) * 8 + jj] = acc[jj];
        __syncthreads();

        {
            float sum = 0.0f;
#pragma unroll
            for (int kk = 0; kk < 8; ++kk) sum += red[(kk * 32 + b2) * 8 + jj2];
            float val = xin[(long)(s * BATCH + b2) * NHID + j0 + jj2] + sum + bh;
            float hnew = alpha[s] * tanhf(val);
            hs[(long)(s * BATCH + b2) * NHID + j0 + jj2] = hnew;
        }

        grid_barrier((unsigned)(s + 1));
    }
}

// ---------------- final hidden copy ----------------
__global__ void copy_hidden_kernel(const float* __restrict__ hs, float* __restrict__ dst) {
    int i = blockIdx.x * blockDim.x + threadIdx.x;
    if (i < BATCH * NHID) dst[i] = hs[(long)(SEQ - 1) * BATCH * NHID + i];
}

// ---------------- launch ----------------
extern "C" void kernel_launch(void* const* d_in, const int* in_sizes, int n_in,
                              void* d_out, int out_size)
{
    const int*   input  = (const int*)  d_in[0];
    const float* hidden = (const float*)d_in[1];
    const float* emb_W  = (const float*)d_in[2];
    const float* W_ih   = (const float*)d_in[3];
    const float* W_hh   = (const float*)d_in[4];
    const float* b_ih   = (const float*)d_in[5];
    const float* b_hh   = (const float*)d_in[6];
    const float* alpha  = (const float*)d_in[7];
    const float* dec_W  = (const float*)d_in[8];
    const float* dec_b  = (const float*)d_in[9];

    float* decoded  = (float*)d_out;                          // [S,B,NTOKEN]
    float* hidden_f = (float*)d_out + (long)MROWS * NTOKEN;   // [B,NHID]

    void *xin_p, *hs_p, *hs32_p, *decw32_p;
    cudaGetSymbolAddress(&xin_p,    g_xin);
    cudaGetSymbolAddress(&hs_p,     g_hs);
    cudaGetSymbolAddress(&hs32_p,   g_hs_t32);
    cudaGetSymbolAddress(&decw32_p, g_decW_t32);
    float* xin     = (float*)xin_p;
    float* hs      = (float*)hs_p;
    float* hs32    = (float*)hs32_p;
    float* decw32  = (float*)decw32_p;

    const int scan_smem = (8 * 1024 + 32 * HS_STRIDE + 2048) * (int)sizeof(float);
    cudaFuncSetAttribute(scan_kernel, cudaFuncAttributeMaxDynamicSharedMemorySize, scan_smem);
    const int tf32_smem = 2 * (TBM + TBN) * TSTR * (int)sizeof(float); // 73728
    cudaFuncSetAttribute(gemm_tf32_kernel, cudaFuncAttributeMaxDynamicSharedMemorySize, tf32_smem);

    // 0) convert dec_W -> tf32 bits (independent of the recurrence)
    cvt_tf32_kernel<<<2048, 256>>>(dec_W, decw32, (long)NTOKEN * NHID);

    // 1) xin = emb_W[input] @ W_ih^T + b_ih   [4096 x 1024]  (fp32)
    gemm_tn_kernel<true><<<dim3(NHID / 128, MROWS / 128), 256>>>(
        emb_W, input, W_ih, b_ih, xin, MROWS, NHID, NINP);

    // 2) recurrence
    reset_barrier_kernel<<<1, 1>>>();
    scan_kernel<<<128, 256, scan_smem>>>(xin, hidden, W_hh, b_hh, alpha, hs);

    // 3) final hidden
    copy_hidden_kernel<<<(BATCH * NHID + 255) / 256, 256>>>(hs, hidden_f);

    // 4) hs -> tf32 bits
    cvt_tf32_kernel<<<1024, 256>>>(hs, hs32, (long)MROWS * NHID);

    // 5) decoder on tensor cores: decoded = hs @ dec_W^T + dec_b  [4096 x 32000]
    gemm_tf32_kernel<<<dim3(MROWS / TBM, NTOKEN / TBN), 256, tf32_smem>>>(
        hs32, decw32, dec_b, decoded, MROWS, NTOKEN, NHID);
}

// round 4
// speedup vs baseline: 2.6747x; 1.0936x over previous
#include <cuda_runtime.h>
#include <cuda_bf16.h>
#include <math.h>
#include <stdint.h>

// Problem constants
#define SEQ    128
#define BATCH  32
#define NTOKEN 32000
#define NINP   1024
#define NHID   1024
#define MROWS  (SEQ * BATCH)          // 4096

// ---------------- scratch (no runtime allocation allowed) ----------------
__device__ float g_xin[MROWS * NHID];        // 16 MB
__device__ float g_hs [MROWS * NHID];        // 16 MB
__device__ float g_hs_t32[MROWS * NHID];     // 16 MB (tf32 bits)
__device__ float g_decW_t32[NTOKEN * NHID];  // 131 MB (tf32 bits)
__device__ unsigned g_arrive;
__device__ unsigned g_release;

// ---------------- helpers ----------------
__device__ __forceinline__ uint32_t smem_u32(const void* p) {
    return (uint32_t)__cvta_generic_to_shared(p);
}

#define LDSM_X4(r0, r1, r2, r3, addr) \
    asm volatile("ldmatrix.sync.aligned.m8n8.x4.shared.b16 {%0,%1,%2,%3}, [%4];" \
        : "=r"(r0), "=r"(r1), "=r"(r2), "=r"(r3) : "r"(addr))

// ---------------- reset barrier counters (each launch/replay) ----------------
__global__ void reset_barrier_kernel() {
    g_arrive = 0u;
    g_release = 0u;
}

// ---------------- fp32 -> tf32 bit conversion (elementwise) ----------------
__global__ __launch_bounds__(256)
void cvt_tf32_kernel(const float* __restrict__ in, float* __restrict__ out, long n)
{
    long i = ((long)blockIdx.x * blockDim.x + threadIdx.x) * 4;
    long stride = (long)gridDim.x * blockDim.x * 4;
    for (; i < n; i += stride) {
        float4 v = *(const float4*)(in + i);
        uint4 o;
        asm("cvt.rna.tf32.f32 %0, %1;" : "=r"(o.x) : "f"(v.x));
        asm("cvt.rna.tf32.f32 %0, %1;" : "=r"(o.y) : "f"(v.y));
        asm("cvt.rna.tf32.f32 %0, %1;" : "=r"(o.z) : "f"(v.z));
        asm("cvt.rna.tf32.f32 %0, %1;" : "=r"(o.w) : "f"(v.w));
        *(uint4*)(out + i) = o;
    }
}

// ---------------- fp32 SIMT GEMM for xin: C = A[M,K]*B[N,K]^T + bias ----
template <bool GATHER>
__global__ __launch_bounds__(256)
void gemm_tn_kernel(const float* __restrict__ A,
                    const int*   __restrict__ rows,
                    const float* __restrict__ B,
                    const float* __restrict__ bias,
                    float*       __restrict__ C,
                    int M, int N, int K)
{
    __shared__ float As[16][128];
    __shared__ float Bs[16][128];

    const int t  = threadIdx.x;
    const int m0 = blockIdx.y * 128;
    const int n0 = blockIdx.x * 128;

    const int tn = t & 15;
    const int tm = t >> 4;

    const int lr = t >> 1;
    const int kq = (t & 1) * 8;

    long a_row = GATHER ? (long)rows[m0 + lr] : (long)(m0 + lr);
    const float* Ap = A + a_row * (long)K;
    const float* Bp = B + (long)(n0 + lr) * (long)K;

    float acc[8][8];
#pragma unroll
    for (int i = 0; i < 8; ++i)
#pragma unroll
        for (int j = 0; j < 8; ++j) acc[i][j] = 0.0f;

    for (int k0 = 0; k0 < K; k0 += 16) {
        float4 a0 = *(const float4*)(Ap + k0 + kq);
        float4 a1 = *(const float4*)(Ap + k0 + kq + 4);
        float4 b0 = *(const float4*)(Bp + k0 + kq);
        float4 b1 = *(const float4*)(Bp + k0 + kq + 4);
        __syncthreads();
        As[kq + 0][lr] = a0.x; As[kq + 1][lr] = a0.y;
        As[kq + 2][lr] = a0.z; As[kq + 3][lr] = a0.w;
        As[kq + 4][lr] = a1.x; As[kq + 5][lr] = a1.y;
        As[kq + 6][lr] = a1.z; As[kq + 7][lr] = a1.w;
        Bs[kq + 0][lr] = b0.x; Bs[kq + 1][lr] = b0.y;
        Bs[kq + 2][lr] = b0.z; Bs[kq + 3][lr] = b0.w;
        Bs[kq + 4][lr] = b1.x; Bs[kq + 5][lr] = b1.y;
        Bs[kq + 6][lr] = b1.z; Bs[kq + 7][lr] = b1.w;
        __syncthreads();

#pragma unroll
        for (int k = 0; k < 16; ++k) {
            float4 af0 = *(const float4*)&As[k][tm * 8];
            float4 af1 = *(const float4*)&As[k][tm * 8 + 4];
            float4 bf0 = *(const float4*)&Bs[k][tn * 8];
            float4 bf1 = *(const float4*)&Bs[k][tn * 8 + 4];
            float av[8] = {af0.x, af0.y, af0.z, af0.w, af1.x, af1.y, af1.z, af1.w};
            float bv[8] = {bf0.x, bf0.y, bf0.z, bf0.w, bf1.x, bf1.y, bf1.z, bf1.w};
#pragma unroll
            for (int i = 0; i < 8; ++i)
#pragma unroll
                for (int j = 0; j < 8; ++j)
                    acc[i][j] = fmaf(av[i], bv[j], acc[i][j]);
        }
    }

    float bb[8];
#pragma unroll
    for (int j = 0; j < 8; ++j) bb[j] = bias[n0 + tn * 8 + j];

#pragma unroll
    for (int i = 0; i < 8; ++i) {
        long crow = (long)(m0 + tm * 8 + i) * (long)N + n0 + tn * 8;
        float4 v0, v1;
        v0.x = acc[i][0] + bb[0]; v0.y = acc[i][1] + bb[1];
        v0.z = acc[i][2] + bb[2]; v0.w = acc[i][3] + bb[3];
        v1.x = acc[i][4] + bb[4]; v1.y = acc[i][5] + bb[5];
        v1.z = acc[i][6] + bb[6]; v1.w = acc[i][7] + bb[7];
        *(float4*)(C + crow)     = v0;
        *(float4*)(C + crow + 4) = v1;
    }
}

// ============ tf32 mma.sync decoder GEMM with ldmatrix fragments ============
// C[M,N] = A[M,K]*B[N,K]^T + bias.  CTA tile 128x128x32, 8 warps (64x32 each).
// Smem: swizzled 128B rows (32 floats), chunk' = kc ^ (row&7). 2-stage cp.async.
#define DBM 128
#define DBN 128
#define DBK 32
#define A_ST (DBM * DBK * 4)   // 16 KB
#define B_ST (DBN * DBK * 4)   // 16 KB
#define DEC_SMEM (2 * (A_ST + B_ST))   // 64 KB

__global__ __launch_bounds__(256, 2)
void gemm_tf32_ldsm(const float* __restrict__ A,
                    const float* __restrict__ B,
                    const float* __restrict__ bias,
                    float*       __restrict__ C,
                    int M, int N, int K)
{
    extern __shared__ __align__(1024) char smem[];
    const uint32_t sA = smem_u32(smem);
    const uint32_t sB = sA + 2 * A_ST;

    const int t    = threadIdx.x;
    const int warp = t >> 5;
    const int lane = t & 31;
    const int m0   = blockIdx.x * DBM;
    const int n0   = blockIdx.y * DBN;
    const int wm   = warp & 1;      // 2 m-subtiles of 64
    const int wn   = warp >> 1;     // 4 n-subtiles of 32
    const int g    = lane >> 2;
    const int tg   = lane & 3;

    // ldmatrix lane geometry
    const int mat = lane >> 3;      // 0..3
    const int sub = lane & 7;       // 0..7

    // A: matrix(0,1) -> row groups (+0,+8) at chunk c; matrix(2,3) -> same rows at c+1
    uint32_t aRowOff[4], aSw[4];
#pragma unroll
    for (int mi = 0; mi < 4; ++mi) {
        int r = wm * 64 + mi * 16 + (mat & 1) * 8 + sub;
        aRowOff[mi] = (uint32_t)(r * 128);
        aSw[mi]     = (uint32_t)(r & 7);
    }
    const uint32_t aMatK = (uint32_t)(mat >> 1);

    // B: matrix(0,1) -> ni rows at chunks c,c+1; matrix(2,3) -> ni+1 rows
    uint32_t bRowOff[2], bSw[2];
#pragma unroll
    for (int p = 0; p < 2; ++p) {
        int r = wn * 32 + (p * 2 + (mat >> 1)) * 8 + sub;
        bRowOff[p] = (uint32_t)(r * 128);
        bSw[p]     = (uint32_t)(r & 7);
    }
    const uint32_t bMatK = (uint32_t)(mat & 1);

    float acc[4][4][4];
#pragma unroll
    for (int mi = 0; mi < 4; ++mi)
#pragma unroll
        for (int ni = 0; ni < 4; ++ni)
#pragma unroll
            for (int r = 0; r < 4; ++r) acc[mi][ni][r] = 0.0f;

    // ---- chunk loader: K columns [c*32, c*32+32), swizzled 128B rows ----
    auto load_chunk = [&](int c) {
        const int s  = c & 1;
        const int k0 = c * DBK;
#pragma unroll
        for (int i = 0; i < 4; ++i) {
            int id  = t + i * 256;
            int row = id >> 3;
            int kc  = id & 7;
            uint32_t dst = sA + s * A_ST + (uint32_t)(row * 128 + ((kc ^ (row & 7)) << 4));
            const float* ga = A + (long)(m0 + row) * K + k0 + kc * 4;
            asm volatile("cp.async.cg.shared.global [%0], [%1], 16;" :: "r"(dst), "l"(ga));
            uint32_t dstB = sB + s * B_ST + (uint32_t)(row * 128 + ((kc ^ (row & 7)) << 4));
            const float* gb = B + (long)(n0 + row) * K + k0 + kc * 4;
            asm volatile("cp.async.cg.shared.global [%0], [%1], 16;" :: "r"(dstB), "l"(gb));
        }
        asm volatile("cp.async.commit_group;");
    };

    const int NCHUNK = K / DBK;   // 32
    load_chunk(0);

    for (int c = 0; c < NCHUNK; ++c) {
        const int buf = c & 1;
        if (c + 1 < NCHUNK) {
            load_chunk(c + 1);
            asm volatile("cp.async.wait_group 1;");
        } else {
            asm volatile("cp.async.wait_group 0;");
        }
        __syncthreads();

        const uint32_t Ab = sA + buf * A_ST;
        const uint32_t Bb = sB + buf * B_ST;

#pragma unroll
        for (int kk = 0; kk < 4; ++kk) {
            uint32_t a[4][4];
            uint32_t b[4][2];
            const uint32_t cA = (uint32_t)(kk * 2) + aMatK;
            const uint32_t cB = (uint32_t)(kk * 2) + bMatK;
#pragma unroll
            for (int mi = 0; mi < 4; ++mi) {
                uint32_t addr = Ab + aRowOff[mi] + (((cA ^ aSw[mi])) << 4);
                LDSM_X4(a[mi][0], a[mi][1], a[mi][2], a[mi][3], addr);
            }
#pragma unroll
            for (int p = 0; p < 2; ++p) {
                uint32_t addr = Bb + bRowOff[p] + (((cB ^ bSw[p])) << 4);
                uint32_t r0, r1, r2, r3;
                LDSM_X4(r0, r1, r2, r3, addr);
                b[2 * p][0] = r0;     b[2 * p][1] = r1;
                b[2 * p + 1][0] = r2; b[2 * p + 1][1] = r3;
            }
#pragma unroll
            for (int mi = 0; mi < 4; ++mi)
#pragma unroll
                for (int ni = 0; ni < 4; ++ni) {
                    asm volatile(
                        "mma.sync.aligned.m16n8k8.row.col.f32.tf32.tf32.f32 "
                        "{%0,%1,%2,%3}, {%4,%5,%6,%7}, {%8,%9}, {%0,%1,%2,%3};\n"
                        : "+f"(acc[mi][ni][0]), "+f"(acc[mi][ni][1]),
                          "+f"(acc[mi][ni][2]), "+f"(acc[mi][ni][3])
                        : "r"(a[mi][0]), "r"(a[mi][1]), "r"(a[mi][2]), "r"(a[mi][3]),
                          "r"(b[ni][0]), "r"(b[ni][1]));
                }
        }
        __syncthreads();
    }

    // ---- epilogue: add bias, store ----
#pragma unroll
    for (int mi = 0; mi < 4; ++mi) {
        int rbase = m0 + wm * 64 + mi * 16 + g;
#pragma unroll
        for (int ni = 0; ni < 4; ++ni) {
            int cc = n0 + wn * 32 + ni * 8 + 2 * tg;
            float b0 = bias[cc], b1 = bias[cc + 1];
            float2 v0 = make_float2(acc[mi][ni][0] + b0, acc[mi][ni][1] + b1);
            float2 v1 = make_float2(acc[mi][ni][2] + b0, acc[mi][ni][3] + b1);
            *(float2*)(C + (long)rbase * N + cc)       = v0;
            *(float2*)(C + (long)(rbase + 8) * N + cc) = v1;
        }
    }
}

// ---------------- persistent RNN scan ----------------
__device__ __forceinline__ void grid_barrier(unsigned gen) {
    __syncthreads();
    if (threadIdx.x == 0) {
        __threadfence();
        if (atomicAdd(&g_arrive, 1u) == gridDim.x - 1) {
            g_arrive = 0u;
            __threadfence();
            atomicExch(&g_release, gen);
        } else {
            while (*(volatile unsigned*)&g_release < gen) { }
        }
        __threadfence();
    }
    __syncthreads();
}

__global__ __launch_bounds__(256)
void scan_kernel(const float* __restrict__ xin,
                 const float* __restrict__ h0,
                 const float* __restrict__ W_hh,
                 const float* __restrict__ b_hh,
                 const float* __restrict__ alpha,
                 float*       __restrict__ hs)
{
    extern __shared__ float sm[];
    float* Wsh = sm;                  // 8 * 1024
    float* red = sm + 8 * 1024;       // 8 * 32 * 8

    const int t  = threadIdx.x;
    const int jb = blockIdx.x;
    const int j0 = jb * 8;

    {
        const float4* src = (const float4*)(W_hh + (long)j0 * NHID);
        float4* dst = (float4*)Wsh;
        for (int i = t; i < 8 * NHID / 4; i += 256) dst[i] = src[i];
    }
    __syncthreads();

    const int kg = t >> 5;
    const int b  = t & 31;
    const int b2  = t >> 3;
    const int jj2 = t & 7;
    const float bh = b_hh[j0 + jj2];

    for (int s = 0; s < SEQ; ++s) {
        const float* hprev = (s == 0) ? h0 : (hs + (long)(s - 1) * BATCH * NHID);

        float acc[8];
#pragma unroll
        for (int jj = 0; jj < 8; ++jj) acc[jj] = 0.0f;

        const float* hrow  = hprev + (long)b * NHID + kg * 128;
        const float* wbase = &Wsh[kg * 128];
#pragma unroll 8
        for (int k = 0; k < 128; k += 4) {
            float4 hv = *(const float4*)&hrow[k];
#pragma unroll
            for (int jj = 0; jj < 8; ++jj) {
                float4 wv = *(const float4*)&wbase[jj * NHID + k];
                acc[jj] += hv.x * wv.x + hv.y * wv.y + hv.z * wv.z + hv.w * wv.w;
            }
        }

#pragma unroll
        for (int jj = 0; jj < 8; ++jj) red[(kg * 32 + b) * 8 + jj] = acc[jj];
        __syncthreads();

        {
            float sum = 0.0f;
#pragma unroll
            for (int kk = 0; kk < 8; ++kk) sum += red[(kk * 32 + b2) * 8 + jj2];
            float val = xin[(long)(s * BATCH + b2) * NHID + j0 + jj2] + sum + bh;
            float hnew = alpha[s] * tanhf(val);
            hs[(long)(s * BATCH + b2) * NHID + j0 + jj2] = hnew;
        }

        grid_barrier((unsigned)(s + 1));
    }
}

// ---------------- final hidden copy ----------------
__global__ void copy_hidden_kernel(const float* __restrict__ hs, float* __restrict__ dst) {
    int i = blockIdx.x * blockDim.x + threadIdx.x;
    if (i < BATCH * NHID) dst[i] = hs[(long)(SEQ - 1) * BATCH * NHID + i];
}

// ---------------- launch ----------------
extern "C" void kernel_launch(void* const* d_in, const int* in_sizes, int n_in,
                              void* d_out, int out_size)
{
    const int*   input  = (const int*)  d_in[0];
    const float* hidden = (const float*)d_in[1];
    const float* emb_W  = (const float*)d_in[2];
    const float* W_ih   = (const float*)d_in[3];
    const float* W_hh   = (const float*)d_in[4];
    const float* b_ih   = (const float*)d_in[5];
    const float* b_hh   = (const float*)d_in[6];
    const float* alpha  = (const float*)d_in[7];
    const float* dec_W  = (const float*)d_in[8];
    const float* dec_b  = (const float*)d_in[9];

    float* decoded  = (float*)d_out;                          // [S,B,NTOKEN]
    float* hidden_f = (float*)d_out + (long)MROWS * NTOKEN;   // [B,NHID]

    void *xin_p, *hs_p, *hs32_p, *decw32_p;
    cudaGetSymbolAddress(&xin_p,    g_xin);
    cudaGetSymbolAddress(&hs_p,     g_hs);
    cudaGetSymbolAddress(&hs32_p,   g_hs_t32);
    cudaGetSymbolAddress(&decw32_p, g_decW_t32);
    float* xin     = (float*)xin_p;
    float* hs      = (float*)hs_p;
    float* hs32    = (float*)hs32_p;
    float* decw32  = (float*)decw32_p;

    const int scan_smem = (8 * 1024 + 8 * 32 * 8) * (int)sizeof(float);
    cudaFuncSetAttribute(scan_kernel, cudaFuncAttributeMaxDynamicSharedMemorySize, scan_smem);
    cudaFuncSetAttribute(gemm_tf32_ldsm, cudaFuncAttributeMaxDynamicSharedMemorySize, DEC_SMEM);

    // 0) convert dec_W -> tf32 bits (independent of the recurrence)
    cvt_tf32_kernel<<<2048, 256>>>(dec_W, decw32, (long)NTOKEN * NHID);

    // 1) xin = emb_W[input] @ W_ih^T + b_ih   [4096 x 1024]  (fp32)
    gemm_tn_kernel<true><<<dim3(NHID / 128, MROWS / 128), 256>>>(
        emb_W, input, W_ih, b_ih, xin, MROWS, NHID, NINP);

    // 2) recurrence
    reset_barrier_kernel<<<1, 1>>>();
    scan_kernel<<<128, 256, scan_smem>>>(xin, hidden, W_hh, b_hh, alpha, hs);

    // 3) final hidden
    copy_hidden_kernel<<<(BATCH * NHID + 255) / 256, 256>>>(hs, hidden_f);

    // 4) hs -> tf32 bits
    cvt_tf32_kernel<<<1024, 256>>>(hs, hs32, (long)MROWS * NHID);

    // 5) decoder: decoded = hs @ dec_W^T + dec_b  [4096 x 32000]
    //    m-fastest grid so co-resident CTAs share the B strip through L2
    gemm_tf32_ldsm<<<dim3(MROWS / DBM, NTOKEN / DBN), 256, DEC_SMEM>>>(
        hs32, decw32, dec_b, decoded, MROWS, NTOKEN, NHID);
}

// round 5
// speedup vs baseline: 2.7275x; 1.0197x over previous
#include <cuda_runtime.h>
#include <cuda_bf16.h>
#include <math.h>
#include <stdint.h>

// Problem constants
#define SEQ    128
#define BATCH  32
#define NTOKEN 32000
#define NINP   1024
#define NHID   1024
#define MROWS  (SEQ * BATCH)          // 4096

// ---------------- scratch (no runtime allocation allowed) ----------------
__device__ float g_xin[MROWS * NHID];        // 16 MB
__device__ float g_hs [MROWS * NHID];        // 16 MB
__device__ float g_t32buf[MROWS * NHID];     // 16 MB (tf32 bits: emb32, later hs32)
__device__ float g_decW_t32[NTOKEN * NHID];  // 131 MB (tf32 bits)
__device__ float g_wih_t32[NHID * NINP];     // 4 MB (tf32 bits)
__device__ unsigned g_arrive;
__device__ unsigned g_release;

// ---------------- helpers ----------------
__device__ __forceinline__ uint32_t smem_u32(const void* p) {
    return (uint32_t)__cvta_generic_to_shared(p);
}

#define LDSM_X4(r0, r1, r2, r3, addr) \
    asm volatile("ldmatrix.sync.aligned.m8n8.x4.shared.b16 {%0,%1,%2,%3}, [%4];" \
        : "=r"(r0), "=r"(r1), "=r"(r2), "=r"(r3) : "r"(addr))

// ---------------- reset barrier counters (each launch/replay) ----------------
__global__ void reset_barrier_kernel() {
    g_arrive = 0u;
    g_release = 0u;
}

// ---------------- fp32 -> tf32 bit conversion (elementwise) ----------------
__global__ __launch_bounds__(256)
void cvt_tf32_kernel(const float* __restrict__ in, float* __restrict__ out, long n)
{
    long i = ((long)blockIdx.x * blockDim.x + threadIdx.x) * 4;
    long stride = (long)gridDim.x * blockDim.x * 4;
    for (; i < n; i += stride) {
        float4 v = *(const float4*)(in + i);
        uint4 o;
        asm("cvt.rna.tf32.f32 %0, %1;" : "=r"(o.x) : "f"(v.x));
        asm("cvt.rna.tf32.f32 %0, %1;" : "=r"(o.y) : "f"(v.y));
        asm("cvt.rna.tf32.f32 %0, %1;" : "=r"(o.z) : "f"(v.z));
        asm("cvt.rna.tf32.f32 %0, %1;" : "=r"(o.w) : "f"(v.w));
        *(uint4*)(out + i) = o;
    }
}

// ---------------- embedding gather + tf32 convert ----------------
// out[i, :] = tf32(emb_W[input[i], :]), i in [0, MROWS)
__global__ __launch_bounds__(256)
void gather_emb_tf32_kernel(const int* __restrict__ input,
                            const float* __restrict__ emb_W,
                            float* __restrict__ out)
{
    long idx = (long)blockIdx.x * blockDim.x + threadIdx.x;   // one float4 each
    int row = (int)(idx >> 8);            // 256 float4 per row (NINP/4)
    int c4  = (int)(idx & 255);
    int tok = input[row];
    float4 v = *(const float4*)(emb_W + (long)tok * NINP + c4 * 4);
    uint4 o;
    asm("cvt.rna.tf32.f32 %0, %1;" : "=r"(o.x) : "f"(v.x));
    asm("cvt.rna.tf32.f32 %0, %1;" : "=r"(o.y) : "f"(v.y));
    asm("cvt.rna.tf32.f32 %0, %1;" : "=r"(o.z) : "f"(v.z));
    asm("cvt.rna.tf32.f32 %0, %1;" : "=r"(o.w) : "f"(v.w));
    *(uint4*)(out + (long)row * NINP + c4 * 4) = o;
}

// ============ tf32 mma.sync GEMM with ldmatrix fragments ============
// C[M,N] = A[M,K]*B[N,K]^T + bias.  CTA tile 128x128x32, 8 warps (64x32 each).
// Smem: swizzled 128B rows (32 floats), chunk' = kc ^ (row&7). 3-stage cp.async.
#define DBM 128
#define DBN 128
#define DBK 32
#define NSTG 3
#define A_ST (DBM * DBK * 4)   // 16 KB
#define B_ST (DBN * DBK * 4)   // 16 KB
#define DEC_SMEM (NSTG * (A_ST + B_ST))   // 96 KB

__global__ __launch_bounds__(256, 2)
void gemm_tf32_ldsm(const float* __restrict__ A,
                    const float* __restrict__ B,
                    const float* __restrict__ bias,
                    float*       __restrict__ C,
                    int M, int N, int K)
{
    extern __shared__ __align__(1024) char smem[];
    const uint32_t sA = smem_u32(smem);
    const uint32_t sB = sA + NSTG * A_ST;

    const int t    = threadIdx.x;
    const int warp = t >> 5;
    const int lane = t & 31;
    const int m0   = blockIdx.x * DBM;
    const int n0   = blockIdx.y * DBN;
    const int wm   = warp & 1;      // 2 m-subtiles of 64
    const int wn   = warp >> 1;     // 4 n-subtiles of 32
    const int g    = lane >> 2;
    const int tg   = lane & 3;

    // ldmatrix lane geometry
    const int mat = lane >> 3;      // 0..3
    const int sub = lane & 7;       // 0..7

    // A: matrix(0,1) -> row groups (+0,+8) at chunk c; matrix(2,3) -> same rows at c+1
    uint32_t aRowOff[4], aSw[4];
#pragma unroll
    for (int mi = 0; mi < 4; ++mi) {
        int r = wm * 64 + mi * 16 + (mat & 1) * 8 + sub;
        aRowOff[mi] = (uint32_t)(r * 128);
        aSw[mi]     = (uint32_t)(r & 7);
    }
    const uint32_t aMatK = (uint32_t)(mat >> 1);

    // B: matrix(0,1) -> ni rows at chunks c,c+1; matrix(2,3) -> ni+1 rows
    uint32_t bRowOff[2], bSw[2];
#pragma unroll
    for (int p = 0; p < 2; ++p) {
        int r = wn * 32 + (p * 2 + (mat >> 1)) * 8 + sub;
        bRowOff[p] = (uint32_t)(r * 128);
        bSw[p]     = (uint32_t)(r & 7);
    }
    const uint32_t bMatK = (uint32_t)(mat & 1);

    float acc[4][4][4];
#pragma unroll
    for (int mi = 0; mi < 4; ++mi)
#pragma unroll
        for (int ni = 0; ni < 4; ++ni)
#pragma unroll
            for (int r = 0; r < 4; ++r) acc[mi][ni][r] = 0.0f;

    // ---- chunk loader: K columns [c*32, c*32+32), swizzled 128B rows ----
    auto load_chunk = [&](int c) {
        const int s  = c % NSTG;
        const int k0 = c * DBK;
#pragma unroll
        for (int i = 0; i < 4; ++i) {
            int id  = t + i * 256;
            int row = id >> 3;
            int kc  = id & 7;
            uint32_t sw = (uint32_t)(row * 128 + ((kc ^ (row & 7)) << 4));
            uint32_t dst = sA + s * A_ST + sw;
            const float* ga = A + (long)(m0 + row) * K + k0 + kc * 4;
            asm volatile("cp.async.cg.shared.global [%0], [%1], 16;" :: "r"(dst), "l"(ga));
            uint32_t dstB = sB + s * B_ST + sw;
            const float* gb = B + (long)(n0 + row) * K + k0 + kc * 4;
            asm volatile("cp.async.cg.shared.global [%0], [%1], 16;" :: "r"(dstB), "l"(gb));
        }
        asm volatile("cp.async.commit_group;");
    };

    const int NCHUNK = K / DBK;   // 32
    load_chunk(0);
    load_chunk(1);
    load_chunk(2);

    for (int c = 0; c < NCHUNK; ++c) {
        const int buf = c % NSTG;
        asm volatile("cp.async.wait_group 2;");   // chunk c resident
        __syncthreads();

        const uint32_t Ab = sA + buf * A_ST;
        const uint32_t Bb = sB + buf * B_ST;

#pragma unroll
        for (int kk = 0; kk < 4; ++kk) {
            uint32_t a[4][4];
            uint32_t b[4][2];
            const uint32_t cA = (uint32_t)(kk * 2) + aMatK;
            const uint32_t cB = (uint32_t)(kk * 2) + bMatK;
#pragma unroll
            for (int mi = 0; mi < 4; ++mi) {
                uint32_t addr = Ab + aRowOff[mi] + (((cA ^ aSw[mi])) << 4);
                LDSM_X4(a[mi][0], a[mi][1], a[mi][2], a[mi][3], addr);
            }
#pragma unroll
            for (int p = 0; p < 2; ++p) {
                uint32_t addr = Bb + bRowOff[p] + (((cB ^ bSw[p])) << 4);
                uint32_t r0, r1, r2, r3;
                LDSM_X4(r0, r1, r2, r3, addr);
                b[2 * p][0] = r0;     b[2 * p][1] = r1;
                b[2 * p + 1][0] = r2; b[2 * p + 1][1] = r3;
            }
#pragma unroll
            for (int mi = 0; mi < 4; ++mi)
#pragma unroll
                for (int ni = 0; ni < 4; ++ni) {
                    asm volatile(
                        "mma.sync.aligned.m16n8k8.row.col.f32.tf32.tf32.f32 "
                        "{%0,%1,%2,%3}, {%4,%5,%6,%7}, {%8,%9}, {%0,%1,%2,%3};\n"
                        : "+f"(acc[mi][ni][0]), "+f"(acc[mi][ni][1]),
                          "+f"(acc[mi][ni][2]), "+f"(acc[mi][ni][3])
                        : "r"(a[mi][0]), "r"(a[mi][1]), "r"(a[mi][2]), "r"(a[mi][3]),
                          "r"(b[ni][0]), "r"(b[ni][1]));
                }
        }
        __syncthreads();   // all warps done reading stage buf

        if (c + NSTG < NCHUNK) {
            load_chunk(c + NSTG);
        } else {
            asm volatile("cp.async.commit_group;");  // uniform group accounting
        }
    }

    // ---- epilogue: add bias, store ----
#pragma unroll
    for (int mi = 0; mi < 4; ++mi) {
        int rbase = m0 + wm * 64 + mi * 16 + g;
#pragma unroll
        for (int ni = 0; ni < 4; ++ni) {
            int cc = n0 + wn * 32 + ni * 8 + 2 * tg;
            float b0 = bias[cc], b1 = bias[cc + 1];
            float2 v0 = make_float2(acc[mi][ni][0] + b0, acc[mi][ni][1] + b1);
            float2 v1 = make_float2(acc[mi][ni][2] + b0, acc[mi][ni][3] + b1);
            *(float2*)(C + (long)rbase * N + cc)       = v0;
            *(float2*)(C + (long)(rbase + 8) * N + cc) = v1;
        }
    }
}

// ---------------- persistent RNN scan ----------------
__device__ __forceinline__ void grid_barrier(unsigned gen) {
    __syncthreads();
    if (threadIdx.x == 0) {
        __threadfence();
        if (atomicAdd(&g_arrive, 1u) == gridDim.x - 1) {
            g_arrive = 0u;
            __threadfence();
            atomicExch(&g_release, gen);
        } else {
            while (*(volatile unsigned*)&g_release < gen) { }
        }
        __threadfence();
    }
    __syncthreads();
}

__global__ __launch_bounds__(256)
void scan_kernel(const float* __restrict__ xin,
                 const float* __restrict__ h0,
                 const float* __restrict__ W_hh,
                 const float* __restrict__ b_hh,
                 const float* __restrict__ alpha,
                 float*       __restrict__ hs)
{
    extern __shared__ float sm[];
    float* Wsh = sm;                  // 8 * 1024
    float* red = sm + 8 * 1024;       // 8 * 32 * 8

    const int t  = threadIdx.x;
    const int jb = blockIdx.x;
    const int j0 = jb * 8;

    {
        const float4* src = (const float4*)(W_hh + (long)j0 * NHID);
        float4* dst = (float4*)Wsh;
        for (int i = t; i < 8 * NHID / 4; i += 256) dst[i] = src[i];
    }
    __syncthreads();

    const int kg = t >> 5;
    const int b  = t & 31;
    const int b2  = t >> 3;
    const int jj2 = t & 7;
    const float bh = b_hh[j0 + jj2];

    for (int s = 0; s < SEQ; ++s) {
        const float* hprev = (s == 0) ? h0 : (hs + (long)(s - 1) * BATCH * NHID);

        float acc[8];
#pragma unroll
        for (int jj = 0; jj < 8; ++jj) acc[jj] = 0.0f;

        const float* hrow  = hprev + (long)b * NHID + kg * 128;
        const float* wbase = &Wsh[kg * 128];
#pragma unroll 8
        for (int k = 0; k < 128; k += 4) {
            float4 hv = *(const float4*)&hrow[k];
#pragma unroll
            for (int jj = 0; jj < 8; ++jj) {
                float4 wv = *(const float4*)&wbase[jj * NHID + k];
                acc[jj] += hv.x * wv.x + hv.y * wv.y + hv.z * wv.z + hv.w * wv.w;
            }
        }

#pragma unroll
        for (int jj = 0; jj < 8; ++jj) red[(kg * 32 + b) * 8 + jj] = acc[jj];
        __syncthreads();

        {
            float sum = 0.0f;
#pragma unroll
            for (int kk = 0; kk < 8; ++kk) sum += red[(kk * 32 + b2) * 8 + jj2];
            float val = xin[(long)(s * BATCH + b2) * NHID + j0 + jj2] + sum + bh;
            float hnew = alpha[s] * tanhf(val);
            hs[(long)(s * BATCH + b2) * NHID + j0 + jj2] = hnew;
        }

        grid_barrier((unsigned)(s + 1));
    }
}

// ---------------- final hidden copy ----------------
__global__ void copy_hidden_kernel(const float* __restrict__ hs, float* __restrict__ dst) {
    int i = blockIdx.x * blockDim.x + threadIdx.x;
    if (i < BATCH * NHID) dst[i] = hs[(long)(SEQ - 1) * BATCH * NHID + i];
}

// ---------------- launch ----------------
extern "C" void kernel_launch(void* const* d_in, const int* in_sizes, int n_in,
                              void* d_out, int out_size)
{
    const int*   input  = (const int*)  d_in[0];
    const float* hidden = (const float*)d_in[1];
    const float* emb_W  = (const float*)d_in[2];
    const float* W_ih   = (const float*)d_in[3];
    const float* W_hh   = (const float*)d_in[4];
    const float* b_ih   = (const float*)d_in[5];
    const float* b_hh   = (const float*)d_in[6];
    const float* alpha  = (const float*)d_in[7];
    const float* dec_W  = (const float*)d_in[8];
    const float* dec_b  = (const float*)d_in[9];

    float* decoded  = (float*)d_out;                          // [S,B,NTOKEN]
    float* hidden_f = (float*)d_out + (long)MROWS * NTOKEN;   // [B,NHID]

    void *xin_p, *hs_p, *t32_p, *decw32_p, *wih32_p;
    cudaGetSymbolAddress(&xin_p,    g_xin);
    cudaGetSymbolAddress(&hs_p,     g_hs);
    cudaGetSymbolAddress(&t32_p,    g_t32buf);
    cudaGetSymbolAddress(&decw32_p, g_decW_t32);
    cudaGetSymbolAddress(&wih32_p,  g_wih_t32);
    float* xin     = (float*)xin_p;
    float* hs      = (float*)hs_p;
    float* t32     = (float*)t32_p;     // emb32 first, hs32 later
    float* decw32  = (float*)decw32_p;
    float* wih32   = (float*)wih32_p;

    const int scan_smem = (8 * 1024 + 8 * 32 * 8) * (int)sizeof(float);
    cudaFuncSetAttribute(scan_kernel, cudaFuncAttributeMaxDynamicSharedMemorySize, scan_smem);
    cudaFuncSetAttribute(gemm_tf32_ldsm, cudaFuncAttributeMaxDynamicSharedMemorySize, DEC_SMEM);

    // 0) weight conversions (independent of the recurrence)
    cvt_tf32_kernel<<<2048, 256>>>(dec_W, decw32, (long)NTOKEN * NHID);
    cvt_tf32_kernel<<<512, 256>>>(W_ih, wih32, (long)NHID * NINP);

    // 1) emb gather -> tf32, then xin = emb @ W_ih^T + b_ih on tensor cores
    gather_emb_tf32_kernel<<<MROWS * (NINP / 4) / 256, 256>>>(input, emb_W, t32);
    gemm_tf32_ldsm<<<dim3(MROWS / DBM, NHID / DBN), 256, DEC_SMEM>>>(
        t32, wih32, b_ih, xin, MROWS, NHID, NINP);

    // 2) recurrence (fp32)
    reset_barrier_kernel<<<1, 1>>>();
    scan_kernel<<<128, 256, scan_smem>>>(xin, hidden, W_hh, b_hh, alpha, hs);

    // 3) final hidden
    copy_hidden_kernel<<<(BATCH * NHID + 255) / 256, 256>>>(hs, hidden_f);

    // 4) hs -> tf32 bits (reuse t32 buffer)
    cvt_tf32_kernel<<<1024, 256>>>(hs, t32, (long)MROWS * NHID);

    // 5) decoder: decoded = hs @ dec_W^T + dec_b  [4096 x 32000]
    //    m-fastest grid so co-resident CTAs share the B strip through L2
    gemm_tf32_ldsm<<<dim3(MROWS / DBM, NTOKEN / DBN), 256, DEC_SMEM>>>(
        t32, decw32, dec_b, decoded, MROWS, NTOKEN, NHID);
}

// round 6
// speedup vs baseline: 2.8673x; 1.0513x over previous
#include <cuda_runtime.h>
#include <cuda_bf16.h>
#include <math.h>
#include <stdint.h>

// Problem constants
#define SEQ    128
#define BATCH  32
#define NTOKEN 32000
#define NINP   1024
#define NHID   1024
#define MROWS  (SEQ * BATCH)          // 4096

// ---------------- scratch (no runtime allocation allowed) ----------------
__device__ float g_xin[MROWS * NHID];        // 16 MB
__device__ float g_hs [MROWS * NHID];        // 16 MB (fp32, scan-internal)
__device__ float g_t32buf[MROWS * NHID];     // 16 MB (tf32 bits: emb32 then hs32)
__device__ float g_decW_t32[NTOKEN * NHID];  // 131 MB (tf32 bits)
__device__ float g_wih_t32[NHID * NINP];     // 4 MB (tf32 bits)
__device__ unsigned g_arrive;
__device__ unsigned g_release;

// ---------------- helpers ----------------
__device__ __forceinline__ uint32_t smem_u32(const void* p) {
    return (uint32_t)__cvta_generic_to_shared(p);
}
__device__ __forceinline__ uint32_t f2tf32(float x) {
    uint32_t r;
    asm("cvt.rna.tf32.f32 %0, %1;" : "=r"(r) : "f"(x));
    return r;
}

#define LDSM_X4(r0, r1, r2, r3, addr) \
    asm volatile("ldmatrix.sync.aligned.m8n8.x4.shared.b16 {%0,%1,%2,%3}, [%4];" \
        : "=r"(r0), "=r"(r1), "=r"(r2), "=r"(r3) : "r"(addr))

// =============== prep: all conversions + gather + barrier reset =============
// blocks [0, 2048)           : cvt dec_W -> g_decW_t32
// blocks [2048, 2112)        : cvt W_ih  -> g_wih_t32
// blocks [2112, 2240)        : gather emb_W[input] -> g_t32buf (tf32)
// block 0 / thread 0         : reset grid-barrier counters
#define PREP_BLOCKS 2240

__global__ __launch_bounds__(256)
void prep_kernel(const float* __restrict__ dec_W,
                 const float* __restrict__ W_ih,
                 const float* __restrict__ emb_W,
                 const int*   __restrict__ input)
{
    const int bid = blockIdx.x;
    const int t   = threadIdx.x;
    if (bid == 0 && t == 0) { g_arrive = 0u; g_release = 0u; }

    if (bid < 2048) {
        // dec_W: 32000*1024 floats = 8192000 float4; 2048*256 = 524288 threads -> ~15.6 each
        const long n4 = (long)NTOKEN * NHID / 4;
        long i = (long)bid * 256 + t;
        const long stride = 2048L * 256;
        for (; i < n4; i += stride) {
            float4 v = ((const float4*)dec_W)[i];
            uint4 o = { f2tf32(v.x), f2tf32(v.y), f2tf32(v.z), f2tf32(v.w) };
            ((uint4*)g_decW_t32)[i] = o;
        }
    } else if (bid < 2112) {
        // W_ih: 1024*1024/4 = 262144 float4; 64*256 = 16384 threads -> 16 each
        const long n4 = (long)NHID * NINP / 4;
        long i = (long)(bid - 2048) * 256 + t;
        const long stride = 64L * 256;
        for (; i < n4; i += stride) {
            float4 v = ((const float4*)W_ih)[i];
            uint4 o = { f2tf32(v.x), f2tf32(v.y), f2tf32(v.z), f2tf32(v.w) };
            ((uint4*)g_wih_t32)[i] = o;
        }
    } else {
        // gather: 4096 rows * 256 float4 = 1048576 float4; 128*256 = 32768 thr -> 32 each
        const long n4 = (long)MROWS * NINP / 4;
        long i = (long)(bid - 2112) * 256 + t;
        const long stride = 128L * 256;
        for (; i < n4; i += stride) {
            int row = (int)(i >> 8);          // NINP/4 = 256 float4 per row
            int c4  = (int)(i & 255);
            int tok = input[row];
            float4 v = *(const float4*)(emb_W + (long)tok * NINP + c4 * 4);
            uint4 o = { f2tf32(v.x), f2tf32(v.y), f2tf32(v.z), f2tf32(v.w) };
            *(uint4*)(g_t32buf + (long)row * NINP + c4 * 4) = o;
        }
    }
}

// ============ tf32 mma.sync GEMM with ldmatrix fragments ============
// C[M,N] = A[M,K]*B[N,K]^T + bias.  CTA tile 128x128x32, 8 warps (64x32 each).
// Smem: swizzled 128B rows, chunk' = kc ^ (row&7). 3 buffers, 2 groups in
// flight, ONE __syncthreads per chunk (load for c+2 overwrites buf of c-1,
// which every warp has finished once it passes the sync at iter c).
#define DBM 128
#define DBN 128
#define DBK 32
#define NSTG 3
#define A_ST (DBM * DBK * 4)   // 16 KB
#define B_ST (DBN * DBK * 4)   // 16 KB
#define DEC_SMEM (NSTG * (A_ST + B_ST))   // 96 KB

__global__ __launch_bounds__(256, 2)
void gemm_tf32_ldsm(const float* __restrict__ A,
                    const float* __restrict__ B,
                    const float* __restrict__ bias,
                    float*       __restrict__ C,
                    int M, int N, int K)
{
    extern __shared__ __align__(1024) char smem[];
    const uint32_t sA = smem_u32(smem);
    const uint32_t sB = sA + NSTG * A_ST;

    const int t    = threadIdx.x;
    const int warp = t >> 5;
    const int lane = t & 31;
    const int m0   = blockIdx.x * DBM;
    const int n0   = blockIdx.y * DBN;
    const int wm   = warp & 1;      // 2 m-subtiles of 64
    const int wn   = warp >> 1;     // 4 n-subtiles of 32
    const int g    = lane >> 2;
    const int tg   = lane & 3;

    // ldmatrix lane geometry
    const int mat = lane >> 3;      // 0..3
    const int sub = lane & 7;       // 0..7

    uint32_t aRowOff[4], aSw[4];
#pragma unroll
    for (int mi = 0; mi < 4; ++mi) {
        int r = wm * 64 + mi * 16 + (mat & 1) * 8 + sub;
        aRowOff[mi] = (uint32_t)(r * 128);
        aSw[mi]     = (uint32_t)(r & 7);
    }
    const uint32_t aMatK = (uint32_t)(mat >> 1);

    uint32_t bRowOff[2], bSw[2];
#pragma unroll
    for (int p = 0; p < 2; ++p) {
        int r = wn * 32 + (p * 2 + (mat >> 1)) * 8 + sub;
        bRowOff[p] = (uint32_t)(r * 128);
        bSw[p]     = (uint32_t)(r & 7);
    }
    const uint32_t bMatK = (uint32_t)(mat & 1);

    float acc[4][4][4];
#pragma unroll
    for (int mi = 0; mi < 4; ++mi)
#pragma unroll
        for (int ni = 0; ni < 4; ++ni)
#pragma unroll
            for (int r = 0; r < 4; ++r) acc[mi][ni][r] = 0.0f;

    auto load_chunk = [&](int c) {
        const int s  = c % NSTG;
        const int k0 = c * DBK;
#pragma unroll
        for (int i = 0; i < 4; ++i) {
            int id  = t + i * 256;
            int row = id >> 3;
            int kc  = id & 7;
            uint32_t sw = (uint32_t)(row * 128 + ((kc ^ (row & 7)) << 4));
            uint32_t dst = sA + s * A_ST + sw;
            const float* ga = A + (long)(m0 + row) * K + k0 + kc * 4;
            asm volatile("cp.async.cg.shared.global [%0], [%1], 16;" :: "r"(dst), "l"(ga));
            uint32_t dstB = sB + s * B_ST + sw;
            const float* gb = B + (long)(n0 + row) * K + k0 + kc * 4;
            asm volatile("cp.async.cg.shared.global [%0], [%1], 16;" :: "r"(dstB), "l"(gb));
        }
        asm volatile("cp.async.commit_group;");
    };

    const int NCHUNK = K / DBK;   // 32
    load_chunk(0);
    load_chunk(1);

    for (int c = 0; c < NCHUNK; ++c) {
        const int buf = c % NSTG;
        asm volatile("cp.async.wait_group 1;");   // chunk c resident
        __syncthreads();                          // the ONLY sync per chunk

        // prefetch chunk c+2 into buf (c-1)%3 (finished by all warps)
        if (c + 2 < NCHUNK) {
            load_chunk(c + 2);
        } else {
            asm volatile("cp.async.commit_group;");   // uniform accounting
        }

        const uint32_t Ab = sA + buf * A_ST;
        const uint32_t Bb = sB + buf * B_ST;

#pragma unroll
        for (int kk = 0; kk < 4; ++kk) {
            uint32_t a[4][4];
            uint32_t b[4][2];
            const uint32_t cA = (uint32_t)(kk * 2) + aMatK;
            const uint32_t cB = (uint32_t)(kk * 2) + bMatK;
#pragma unroll
            for (int mi = 0; mi < 4; ++mi) {
                uint32_t addr = Ab + aRowOff[mi] + (((cA ^ aSw[mi])) << 4);
                LDSM_X4(a[mi][0], a[mi][1], a[mi][2], a[mi][3], addr);
            }
#pragma unroll
            for (int p = 0; p < 2; ++p) {
                uint32_t addr = Bb + bRowOff[p] + (((cB ^ bSw[p])) << 4);
                uint32_t r0, r1, r2, r3;
                LDSM_X4(r0, r1, r2, r3, addr);
                b[2 * p][0] = r0;     b[2 * p][1] = r1;
                b[2 * p + 1][0] = r2; b[2 * p + 1][1] = r3;
            }
#pragma unroll
            for (int mi = 0; mi < 4; ++mi)
#pragma unroll
                for (int ni = 0; ni < 4; ++ni) {
                    asm volatile(
                        "mma.sync.aligned.m16n8k8.row.col.f32.tf32.tf32.f32 "
                        "{%0,%1,%2,%3}, {%4,%5,%6,%7}, {%8,%9}, {%0,%1,%2,%3};\n"
                        : "+f"(acc[mi][ni][0]), "+f"(acc[mi][ni][1]),
                          "+f"(acc[mi][ni][2]), "+f"(acc[mi][ni][3])
                        : "r"(a[mi][0]), "r"(a[mi][1]), "r"(a[mi][2]), "r"(a[mi][3]),
                          "r"(b[ni][0]), "r"(b[ni][1]));
                }
        }
        // no trailing sync: next iteration's wait+sync provides the ordering
    }

    // ---- epilogue: add bias, store ----
#pragma unroll
    for (int mi = 0; mi < 4; ++mi) {
        int rbase = m0 + wm * 64 + mi * 16 + g;
#pragma unroll
        for (int ni = 0; ni < 4; ++ni) {
            int cc = n0 + wn * 32 + ni * 8 + 2 * tg;
            float b0 = bias[cc], b1 = bias[cc + 1];
            float2 v0 = make_float2(acc[mi][ni][0] + b0, acc[mi][ni][1] + b1);
            float2 v1 = make_float2(acc[mi][ni][2] + b0, acc[mi][ni][3] + b1);
            *(float2*)(C + (long)rbase * N + cc)       = v0;
            *(float2*)(C + (long)(rbase + 8) * N + cc) = v1;
        }
    }
}

// ---------------- persistent RNN scan ----------------
__device__ __forceinline__ void grid_barrier(unsigned gen) {
    __syncthreads();
    if (threadIdx.x == 0) {
        __threadfence();
        if (atomicAdd(&g_arrive, 1u) == gridDim.x - 1) {
            g_arrive = 0u;
            __threadfence();
            atomicExch(&g_release, gen);
        } else {
            while (*(volatile unsigned*)&g_release < gen) { }
        }
        __threadfence();
    }
    __syncthreads();
}

// Writes: hs (fp32, for the recurrence), hs32 (tf32 bits, for the decoder),
// hidden_f (final hidden state) at s == SEQ-1.
__global__ __launch_bounds__(256)
void scan_kernel(const float* __restrict__ xin,
                 const float* __restrict__ h0,
                 const float* __restrict__ W_hh,
                 const float* __restrict__ b_hh,
                 const float* __restrict__ alpha,
                 float*       __restrict__ hs,
                 float*       __restrict__ hs32,
                 float*       __restrict__ hidden_f)
{
    extern __shared__ float sm[];
    float* Wsh = sm;                  // 8 * 1024
    float* red = sm + 8 * 1024;       // 8 * 32 * 8

    const int t  = threadIdx.x;
    const int jb = blockIdx.x;
    const int j0 = jb * 8;

    {
        const float4* src = (const float4*)(W_hh + (long)j0 * NHID);
        float4* dst = (float4*)Wsh;
        for (int i = t; i < 8 * NHID / 4; i += 256) dst[i] = src[i];
    }
    __syncthreads();

    const int kg = t >> 5;
    const int b  = t & 31;
    const int b2  = t >> 3;
    const int jj2 = t & 7;
    const float bh = b_hh[j0 + jj2];

    for (int s = 0; s < SEQ; ++s) {
        const float* hprev = (s == 0) ? h0 : (hs + (long)(s - 1) * BATCH * NHID);

        float acc[8];
#pragma unroll
        for (int jj = 0; jj < 8; ++jj) acc[jj] = 0.0f;

        const float* hrow  = hprev + (long)b * NHID + kg * 128;
        const float* wbase = &Wsh[kg * 128];
#pragma unroll 8
        for (int k = 0; k < 128; k += 4) {
            float4 hv = *(const float4*)&hrow[k];
#pragma unroll
            for (int jj = 0; jj < 8; ++jj) {
                float4 wv = *(const float4*)&wbase[jj * NHID + k];
                acc[jj] += hv.x * wv.x + hv.y * wv.y + hv.z * wv.z + hv.w * wv.w;
            }
        }

#pragma unroll
        for (int jj = 0; jj < 8; ++jj) red[(kg * 32 + b) * 8 + jj] = acc[jj];
        __syncthreads();

        {
            float sum = 0.0f;
#pragma unroll
            for (int kk = 0; kk < 8; ++kk) sum += red[(kk * 32 + b2) * 8 + jj2];
            long idx = (long)(s * BATCH + b2) * NHID + j0 + jj2;
            float val = xin[idx] + sum + bh;
            float hnew = alpha[s] * tanhf(val);
            hs[idx] = hnew;
            ((uint32_t*)hs32)[idx] = f2tf32(hnew);
            if (s == SEQ - 1) hidden_f[(long)b2 * NHID + j0 + jj2] = hnew;
        }

        grid_barrier((unsigned)(s + 1));
    }
}

// ---------------- launch ----------------
extern "C" void kernel_launch(void* const* d_in, const int* in_sizes, int n_in,
                              void* d_out, int out_size)
{
    const int*   input  = (const int*)  d_in[0];
    const float* hidden = (const float*)d_in[1];
    const float* emb_W  = (const float*)d_in[2];
    const float* W_ih   = (const float*)d_in[3];
    const float* W_hh   = (const float*)d_in[4];
    const float* b_ih   = (const float*)d_in[5];
    const float* b_hh   = (const float*)d_in[6];
    const float* alpha  = (const float*)d_in[7];
    const float* dec_W  = (const float*)d_in[8];
    const float* dec_b  = (const float*)d_in[9];

    float* decoded  = (float*)d_out;                          // [S,B,NTOKEN]
    float* hidden_f = (float*)d_out + (long)MROWS * NTOKEN;   // [B,NHID]

    void *xin_p, *hs_p, *t32_p, *decw32_p, *wih32_p;
    cudaGetSymbolAddress(&xin_p,    g_xin);
    cudaGetSymbolAddress(&hs_p,     g_hs);
    cudaGetSymbolAddress(&t32_p,    g_t32buf);
    cudaGetSymbolAddress(&decw32_p, g_decW_t32);
    cudaGetSymbolAddress(&wih32_p,  g_wih_t32);
    float* xin     = (float*)xin_p;
    float* hs      = (float*)hs_p;
    float* t32     = (float*)t32_p;     // emb32 first, hs32 later (xin GEMM
                                        // consumes emb32 before scan overwrites)
    float* decw32  = (float*)decw32_p;
    float* wih32   = (float*)wih32_p;

    const int scan_smem = (8 * 1024 + 8 * 32 * 8) * (int)sizeof(float);
    cudaFuncSetAttribute(scan_kernel, cudaFuncAttributeMaxDynamicSharedMemorySize, scan_smem);
    cudaFuncSetAttribute(gemm_tf32_ldsm, cudaFuncAttributeMaxDynamicSharedMemorySize, DEC_SMEM);

    // 1) prep: dec_W/W_ih tf32 conversions + emb gather (tf32) + barrier reset
    prep_kernel<<<PREP_BLOCKS, 256>>>(dec_W, W_ih, emb_W, input);

    // 2) xin = emb @ W_ih^T + b_ih on tensor cores [4096 x 1024]
    gemm_tf32_ldsm<<<dim3(MROWS / DBM, NHID / DBN), 256, DEC_SMEM>>>(
        t32, wih32, b_ih, xin, MROWS, NHID, NINP);

    // 3) recurrence (fp32); emits tf32 hs into t32 and hidden_f directly
    scan_kernel<<<128, 256, scan_smem>>>(xin, hidden, W_hh, b_hh, alpha,
                                         hs, t32, hidden_f);

    // 4) decoder: decoded = hs @ dec_W^T + dec_b  [4096 x 32000]  (ncu target)
    gemm_tf32_ldsm<<<dim3(MROWS / DBM, NTOKEN / DBN), 256, DEC_SMEM>>>(
        t32, decw32, dec_b, decoded, MROWS, NTOKEN, NHID);
}